// round 6
// baseline (speedup 1.0000x reference)
#include <cuda_runtime.h>
#include <cuda_bf16.h>

#define IN_DIM 128
#define HID 32
#define NEG_SLOPE 0.2f
#define MAXN 100000
#define MAXE 1600000
#define SB 1024
#define TB 256

typedef unsigned long long u64;

// Scratch (device globals — no allocation allowed)
__device__ float g_h[MAXN * HID];
__device__ float g_el[MAXN];
__device__ float g_er[MAXN];
__device__ float g_agg[MAXN * HID];
__device__ int   g_cnt[MAXN];
__device__ int   g_rowptr[MAXN + 1];
__device__ int   g_fill[MAXN];
__device__ int   g_csrc[MAXE];
__device__ int   g_bsum[(MAXN + SB - 1) / SB + 1];

// ---- packed f32x2 helpers (Blackwell FFMA2: only reachable via PTX) -------
__device__ __forceinline__ u64 pk2(float lo, float hi) {
    u64 r; asm("mov.b64 %0, {%1, %2};" : "=l"(r) : "f"(lo), "f"(hi)); return r;
}
__device__ __forceinline__ void fma2(u64& d, u64 a, u64 b) {
    asm("fma.rn.f32x2 %0, %1, %2, %0;" : "+l"(d) : "l"(a), "l"(b));
}
__device__ __forceinline__ float2 upk2(u64 v) {
    float2 f; asm("mov.b64 {%0, %1}, %2;" : "=f"(f.x), "=f"(f.y) : "l"(v)); return f;
}

// ---------------------------------------------------------------------------
// int4-vectorized histogram
__global__ void k_hist(const int* __restrict__ dst, int E) {
    int i = blockIdx.x * blockDim.x + threadIdx.x;
    int i4 = i * 4;
    if (i4 + 3 < E) {
        int4 d = *(const int4*)(dst + i4);
        atomicAdd(&g_cnt[d.x], 1);
        atomicAdd(&g_cnt[d.y], 1);
        atomicAdd(&g_cnt[d.z], 1);
        atomicAdd(&g_cnt[d.w], 1);
    } else {
        for (int e = i4; e < E; e++) atomicAdd(&g_cnt[dst[e]], 1);
    }
}

// --- scan stage 1: per-block exclusive scan + block totals ------------------
__device__ __forceinline__ int block_incl_scan(int v, int* warpsums) {
    int lane = threadIdx.x & 31, wid = threadIdx.x >> 5;
#pragma unroll
    for (int o = 1; o < 32; o <<= 1) {
        int u = __shfl_up_sync(0xffffffffu, v, o);
        if (lane >= o) v += u;
    }
    if (lane == 31) warpsums[wid] = v;
    __syncthreads();
    if (wid == 0) {
        int w = (lane < (int)(blockDim.x >> 5)) ? warpsums[lane] : 0;
#pragma unroll
        for (int o = 1; o < 32; o <<= 1) {
            int u = __shfl_up_sync(0xffffffffu, w, o);
            if (lane >= o) w += u;
        }
        warpsums[lane] = w;
    }
    __syncthreads();
    if (wid > 0) v += warpsums[wid - 1];
    return v;
}

__global__ void k_scan1(int N) {
    __shared__ int warpsums[32];
    int i = blockIdx.x * SB + threadIdx.x;
    int v = (i < N) ? g_cnt[i] : 0;
    int incl = block_incl_scan(v, warpsums);
    if (i < N) g_rowptr[i] = incl - v;
    if (threadIdx.x == SB - 1) g_bsum[blockIdx.x] = incl;
}

// --- scan stage 2 (fused): each block computes its own offset from g_bsum ---
__global__ void k_scan3(int N, int E) {
    __shared__ int s_off;
    int bid = blockIdx.x;
    if (threadIdx.x < 32) {
        int s = 0;
        for (int j = threadIdx.x; j < bid; j += 32) s += g_bsum[j];
#pragma unroll
        for (int o = 16; o; o >>= 1) s += __shfl_xor_sync(0xffffffffu, s, o);
        if (threadIdx.x == 0) s_off = s;
    }
    __syncthreads();
    int i = bid * SB + threadIdx.x;
    if (i < N) {
        int r = g_rowptr[i] + s_off;
        g_rowptr[i] = r;
        g_fill[i] = r;
    }
    if (i == 0) g_rowptr[N] = E;
}

// --- scatter: standalone, light (16 regs, no smem), 8 edges/thread ----------
__global__ void __launch_bounds__(TB) k_scatter(const int* __restrict__ src,
                                                const int* __restrict__ dst, int E) {
    int i = blockIdx.x * blockDim.x + threadIdx.x;
    int i8 = i * 8;
    if (i8 + 7 < E) {
        int4 s0 = *(const int4*)(src + i8);
        int4 d0 = *(const int4*)(dst + i8);
        int4 s1 = *(const int4*)(src + i8 + 4);
        int4 d1 = *(const int4*)(dst + i8 + 4);
        g_csrc[atomicAdd(&g_fill[d0.x], 1)] = s0.x;
        g_csrc[atomicAdd(&g_fill[d0.y], 1)] = s0.y;
        g_csrc[atomicAdd(&g_fill[d0.z], 1)] = s0.z;
        g_csrc[atomicAdd(&g_fill[d0.w], 1)] = s0.w;
        g_csrc[atomicAdd(&g_fill[d1.x], 1)] = s1.x;
        g_csrc[atomicAdd(&g_fill[d1.y], 1)] = s1.y;
        g_csrc[atomicAdd(&g_fill[d1.z], 1)] = s1.z;
        g_csrc[atomicAdd(&g_fill[d1.w], 1)] = s1.w;
    } else {
        for (int e = i8; e < E; e++)
            g_csrc[atomicAdd(&g_fill[dst[e]], 1)] = src[e];
    }
}

// ---------------------------------------------------------------------------
// Layer-1 GEMM: 4 nodes/warp, transposed padded weights in smem, FFMA2.
#define WT_PITCH (IN_DIM + 4)
__global__ void k_gemm1(const float* __restrict__ x, const float* __restrict__ W,
                        const float* __restrict__ al, const float* __restrict__ ar,
                        int N) {
    __shared__ float Wt[HID * WT_PITCH];
    for (int i = threadIdx.x; i < IN_DIM * HID; i += blockDim.x) {
        int k = i / HID, o = i % HID;
        Wt[o * WT_PITCH + k] = W[i];
    }
    __syncthreads();

    int warp = (blockIdx.x * blockDim.x + threadIdx.x) >> 5;
    int lane = threadIdx.x & 31;
    int n0 = warp * 4;
    if (n0 >= N) return;

    const float4* wv = (const float4*)(Wt + lane * WT_PITCH);
    const float4* x0 = (const float4*)(x + (size_t)n0 * IN_DIM);
    bool v1 = n0 + 1 < N, v2 = n0 + 2 < N, v3 = n0 + 3 < N;

    u64 a01[4] = {0, 0, 0, 0}, a23[4] = {0, 0, 0, 0};
#pragma unroll
    for (int k4 = 0; k4 < IN_DIM / 4; k4++) {
        float4 w = wv[k4];
        u64 w01 = pk2(w.x, w.y), w23 = pk2(w.z, w.w);
        float4 a = x0[k4];
        fma2(a01[0], pk2(a.x, a.y), w01);
        fma2(a23[0], pk2(a.z, a.w), w23);
        if (v1) {
            float4 b = x0[IN_DIM / 4 + k4];
            fma2(a01[1], pk2(b.x, b.y), w01);
            fma2(a23[1], pk2(b.z, b.w), w23);
        }
        if (v2) {
            float4 c = x0[2 * IN_DIM / 4 + k4];
            fma2(a01[2], pk2(c.x, c.y), w01);
            fma2(a23[2], pk2(c.z, c.w), w23);
        }
        if (v3) {
            float4 d = x0[3 * IN_DIM / 4 + k4];
            fma2(a01[3], pk2(d.x, d.y), w01);
            fma2(a23[3], pk2(d.z, d.w), w23);
        }
    }

    float alv = al[lane], arv = ar[lane];
#pragma unroll
    for (int i = 0; i < 4; i++) {
        if (n0 + i >= N) break;
        float2 p = upk2(a01[i]), q = upk2(a23[i]);
        float acc = (p.x + p.y) + (q.x + q.y);
        g_h[(size_t)(n0 + i) * HID + lane] = acc;
        float vl = acc * alv, vr = acc * arv;
#pragma unroll
        for (int o = 16; o; o >>= 1) {
            vl += __shfl_xor_sync(0xffffffffu, vl, o);
            vr += __shfl_xor_sync(0xffffffffu, vr, o);
        }
        if (lane == 0) { g_el[n0 + i] = vl; g_er[n0 + i] = vr; }
    }
}

// ---------------------------------------------------------------------------
// Layer-2 GEMM: h = hmid @ W2 (hmid already ELU'd in g_agg); el, er.
#define WT2_PITCH (HID + 4)
__global__ void k_gemm2(const float* __restrict__ W2,
                        const float* __restrict__ al, const float* __restrict__ ar,
                        int N) {
    __shared__ float Wt[HID * WT2_PITCH];
    for (int i = threadIdx.x; i < HID * HID; i += blockDim.x) {
        int k = i / HID, o = i % HID;
        Wt[o * WT2_PITCH + k] = W2[i];
    }
    __syncthreads();

    int warp = (blockIdx.x * blockDim.x + threadIdx.x) >> 5;
    int lane = threadIdx.x & 31;
    int n0 = warp * 4;
    if (n0 >= N) return;

    const float4* wv = (const float4*)(Wt + lane * WT2_PITCH);
    const float4* x0 = (const float4*)(g_agg + (size_t)n0 * HID);
    bool v1 = n0 + 1 < N, v2 = n0 + 2 < N, v3 = n0 + 3 < N;

    u64 a01[4] = {0, 0, 0, 0}, a23[4] = {0, 0, 0, 0};
#pragma unroll
    for (int k4 = 0; k4 < HID / 4; k4++) {
        float4 w = wv[k4];
        u64 w01 = pk2(w.x, w.y), w23 = pk2(w.z, w.w);
        float4 a = x0[k4];
        fma2(a01[0], pk2(a.x, a.y), w01);
        fma2(a23[0], pk2(a.z, a.w), w23);
        if (v1) {
            float4 b = x0[HID / 4 + k4];
            fma2(a01[1], pk2(b.x, b.y), w01);
            fma2(a23[1], pk2(b.z, b.w), w23);
        }
        if (v2) {
            float4 c = x0[2 * HID / 4 + k4];
            fma2(a01[2], pk2(c.x, c.y), w01);
            fma2(a23[2], pk2(c.z, c.w), w23);
        }
        if (v3) {
            float4 d = x0[3 * HID / 4 + k4];
            fma2(a01[3], pk2(d.x, d.y), w01);
            fma2(a23[3], pk2(d.z, d.w), w23);
        }
    }

    float alv = al[lane], arv = ar[lane];
#pragma unroll
    for (int i = 0; i < 4; i++) {
        if (n0 + i >= N) break;
        float2 p = upk2(a01[i]), q = upk2(a23[i]);
        float acc = (p.x + p.y) + (q.x + q.y);
        g_h[(size_t)(n0 + i) * HID + lane] = acc;
        float vl = acc * alv, vr = acc * arv;
#pragma unroll
        for (int o = 16; o; o >>= 1) {
            vl += __shfl_xor_sync(0xffffffffu, vl, o);
            vr += __shfl_xor_sync(0xffffffffu, vr, o);
        }
        if (lane == 0) { g_el[n0 + i] = vl; g_er[n0 + i] = vr; }
    }
}

// ---------------------------------------------------------------------------
// Fused pull aggregation, (edge-subgroup x dim-quad) lane mapping + FFMA2.
// Epilogue: out = (acc/den) + bias, optionally ELU'd (layer 1).
__global__ void k_agg_csr(float* __restrict__ out, const float* __restrict__ bias,
                          int do_elu, int N) {
    int node = (blockIdx.x * blockDim.x + threadIdx.x) >> 5;
    int lane = threadIdx.x & 31;
    if (node >= N) return;

    int start = g_rowptr[node];
    int end   = g_rowptr[node + 1];
    int deg   = end - start;
    float erd = g_er[node];

    int eg = lane >> 3;   // 0..3
    int dl = lane & 7;    // 0..7

    u64 acc01 = 0, acc23 = 0;
    float denp = 0.f;

    for (int base = start; base < end; base += 32) {
        int idx = base + lane;
        bool valid = idx < end;
        int s_l = valid ? g_csrc[idx] : 0;
        float ex_l = 0.f;
        if (valid) {
            float t = g_el[s_l] + erd;
            t = (t > 0.f) ? t : NEG_SLOPE * t;
            ex_l = __expf(t);
        }
        denp += ex_l;

        int cnt = end - base; if (cnt > 32) cnt = 32;
        for (int j0 = 0; j0 < cnt; j0 += 8) {
            int jA = j0 + eg, jB = j0 + 4 + eg;
            int   sA = __shfl_sync(0xffffffffu, s_l, jA);
            float xA = __shfl_sync(0xffffffffu, ex_l, jA);
            int   sB = __shfl_sync(0xffffffffu, s_l, jB);
            float xB = __shfl_sync(0xffffffffu, ex_l, jB);
            float4 hA = *(const float4*)(g_h + (size_t)sA * HID + dl * 4);
            float4 hB = *(const float4*)(g_h + (size_t)sB * HID + dl * 4);
            u64 xA2 = pk2(xA, xA), xB2 = pk2(xB, xB);
            fma2(acc01, xA2, pk2(hA.x, hA.y));
            fma2(acc23, xA2, pk2(hA.z, hA.w));
            fma2(acc01, xB2, pk2(hB.x, hB.y));
            fma2(acc23, xB2, pk2(hB.z, hB.w));
        }
    }

    float2 p = upk2(acc01), q = upk2(acc23);
    float4 acc = {p.x, p.y, q.x, q.y};
#pragma unroll
    for (int off = 8; off <= 16; off <<= 1) {
        acc.x += __shfl_xor_sync(0xffffffffu, acc.x, off);
        acc.y += __shfl_xor_sync(0xffffffffu, acc.y, off);
        acc.z += __shfl_xor_sync(0xffffffffu, acc.z, off);
        acc.w += __shfl_xor_sync(0xffffffffu, acc.w, off);
    }
#pragma unroll
    for (int off = 16; off; off >>= 1)
        denp += __shfl_xor_sync(0xffffffffu, denp, off);

    if (eg == 0) {
        float inv = (deg > 0) ? 1.f / denp : 0.f;
        float4 b = *(const float4*)(bias + dl * 4);
        float4 r;
        r.x = acc.x * inv + b.x;
        r.y = acc.y * inv + b.y;
        r.z = acc.z * inv + b.z;
        r.w = acc.w * inv + b.w;
        if (do_elu) {
            r.x = (r.x > 0.f) ? r.x : expm1f(r.x);
            r.y = (r.y > 0.f) ? r.y : expm1f(r.y);
            r.z = (r.z > 0.f) ? r.z : expm1f(r.z);
            r.w = (r.w > 0.f) ? r.w : expm1f(r.w);
        }
        *(float4*)(out + (size_t)node * HID + dl * 4) = r;
    }
}

// ---------------------------------------------------------------------------
extern "C" void kernel_launch(void* const* d_in, const int* in_sizes, int n_in,
                              void* d_out, int out_size) {
    const float* features = (const float*)d_in[0];
    const int*   src      = (const int*)d_in[1];
    const int*   dst      = (const int*)d_in[2];
    const float* W1  = (const float*)d_in[3];
    const float* al1 = (const float*)d_in[4];
    const float* ar1 = (const float*)d_in[5];
    const float* b1  = (const float*)d_in[6];
    const float* W2  = (const float*)d_in[7];
    const float* al2 = (const float*)d_in[8];
    const float* ar2 = (const float*)d_in[9];
    const float* b2  = (const float*)d_in[10];
    float* out = (float*)d_out;

    int N = in_sizes[0] / IN_DIM;
    int E = in_sizes[1];

    int gridNodeWarps = (N * 32 + TB - 1) / TB;              // 1 warp/node
    int gridGemm      = (((N + 3) / 4) * 32 + TB - 1) / TB;  // 4 nodes/warp
    int gridE4 = ((E + 3) / 4 + TB - 1) / TB;
    int gridE8 = ((E + 7) / 8 + TB - 1) / TB;
    int nb = (N + SB - 1) / SB;

    float* aggp = nullptr;
    cudaGetSymbolAddress((void**)&aggp, g_agg);
    int* cntp = nullptr;
    cudaGetSymbolAddress((void**)&cntp, g_cnt);

    // ---- CSR build (shared by both layers) ----
    cudaMemsetAsync(cntp, 0, (size_t)N * sizeof(int));
    k_hist<<<gridE4, TB>>>(dst, E);
    k_scan1<<<nb, SB>>>(N);
    k_scan3<<<nb, SB>>>(N, E);
    k_scatter<<<gridE8, TB>>>(src, dst, E);

    // ---- Layer 1 ----
    k_gemm1<<<gridGemm, TB>>>(features, W1, al1, ar1, N);
    k_agg_csr<<<gridNodeWarps, TB>>>(aggp, b1, 1, N);

    // ---- Layer 2 ----
    k_gemm2<<<gridGemm, TB>>>(W2, al2, ar2, N);
    k_agg_csr<<<gridNodeWarps, TB>>>(out, b2, 0, N);
}

// round 7
// speedup vs baseline: 1.0698x; 1.0698x over previous
#include <cuda_runtime.h>
#include <cuda_bf16.h>

#define IN_DIM 128
#define HID 32
#define NEG_SLOPE 0.2f
#define MAXN 100000
#define MAXE 1600000
#define SB 1024
#define TB 256

typedef unsigned long long u64;

// Scratch (device globals — no allocation allowed)
__device__ float g_h[MAXN * HID];     // layer-1 transformed features
__device__ float g_h2[MAXN * HID];    // layer-2 transformed features
__device__ float g_el[MAXN], g_er[MAXN];     // layer-1 logits
__device__ float g_el2[MAXN], g_er2[MAXN];   // layer-2 logits
__device__ int   g_cnt[MAXN];
__device__ int   g_rowptr[MAXN + 1];
__device__ int   g_fill[MAXN];
__device__ int   g_csrc[MAXE];
__device__ int   g_bsum[(MAXN + SB - 1) / SB + 1];

// ---- packed f32x2 helpers (Blackwell FFMA2: only reachable via PTX) -------
__device__ __forceinline__ u64 pk2(float lo, float hi) {
    u64 r; asm("mov.b64 %0, {%1, %2};" : "=l"(r) : "f"(lo), "f"(hi)); return r;
}
__device__ __forceinline__ void fma2(u64& d, u64 a, u64 b) {
    asm("fma.rn.f32x2 %0, %1, %2, %0;" : "+l"(d) : "l"(a), "l"(b));
}
__device__ __forceinline__ float2 upk2(u64 v) {
    float2 f; asm("mov.b64 {%0, %1}, %2;" : "=f"(f.x), "=f"(f.y) : "l"(v)); return f;
}

// ---------------------------------------------------------------------------
__global__ void k_hist(const int* __restrict__ dst, int E) {
    int i = blockIdx.x * blockDim.x + threadIdx.x;
    int i4 = i * 4;
    if (i4 + 3 < E) {
        int4 d = *(const int4*)(dst + i4);
        atomicAdd(&g_cnt[d.x], 1);
        atomicAdd(&g_cnt[d.y], 1);
        atomicAdd(&g_cnt[d.z], 1);
        atomicAdd(&g_cnt[d.w], 1);
    } else {
        for (int e = i4; e < E; e++) atomicAdd(&g_cnt[dst[e]], 1);
    }
}

__device__ __forceinline__ int block_incl_scan(int v, int* warpsums) {
    int lane = threadIdx.x & 31, wid = threadIdx.x >> 5;
#pragma unroll
    for (int o = 1; o < 32; o <<= 1) {
        int u = __shfl_up_sync(0xffffffffu, v, o);
        if (lane >= o) v += u;
    }
    if (lane == 31) warpsums[wid] = v;
    __syncthreads();
    if (wid == 0) {
        int w = (lane < (int)(blockDim.x >> 5)) ? warpsums[lane] : 0;
#pragma unroll
        for (int o = 1; o < 32; o <<= 1) {
            int u = __shfl_up_sync(0xffffffffu, w, o);
            if (lane >= o) w += u;
        }
        warpsums[lane] = w;
    }
    __syncthreads();
    if (wid > 0) v += warpsums[wid - 1];
    return v;
}

__global__ void k_scan1(int N) {
    __shared__ int warpsums[32];
    int i = blockIdx.x * SB + threadIdx.x;
    int v = (i < N) ? g_cnt[i] : 0;
    int incl = block_incl_scan(v, warpsums);
    if (i < N) g_rowptr[i] = incl - v;
    if (threadIdx.x == SB - 1) g_bsum[blockIdx.x] = incl;
}

__global__ void k_scan3(int N, int E) {
    __shared__ int s_off;
    int bid = blockIdx.x;
    if (threadIdx.x < 32) {
        int s = 0;
        for (int j = threadIdx.x; j < bid; j += 32) s += g_bsum[j];
#pragma unroll
        for (int o = 16; o; o >>= 1) s += __shfl_xor_sync(0xffffffffu, s, o);
        if (threadIdx.x == 0) s_off = s;
    }
    __syncthreads();
    int i = bid * SB + threadIdx.x;
    if (i < N) {
        int r = g_rowptr[i] + s_off;
        g_rowptr[i] = r;
        g_fill[i] = r;
    }
    if (i == 0) g_rowptr[N] = E;
}

__global__ void __launch_bounds__(TB) k_scatter(const int* __restrict__ src,
                                                const int* __restrict__ dst, int E) {
    int i = blockIdx.x * blockDim.x + threadIdx.x;
    int i8 = i * 8;
    if (i8 + 7 < E) {
        int4 s0 = *(const int4*)(src + i8);
        int4 d0 = *(const int4*)(dst + i8);
        int4 s1 = *(const int4*)(src + i8 + 4);
        int4 d1 = *(const int4*)(dst + i8 + 4);
        g_csrc[atomicAdd(&g_fill[d0.x], 1)] = s0.x;
        g_csrc[atomicAdd(&g_fill[d0.y], 1)] = s0.y;
        g_csrc[atomicAdd(&g_fill[d0.z], 1)] = s0.z;
        g_csrc[atomicAdd(&g_fill[d0.w], 1)] = s0.w;
        g_csrc[atomicAdd(&g_fill[d1.x], 1)] = s1.x;
        g_csrc[atomicAdd(&g_fill[d1.y], 1)] = s1.y;
        g_csrc[atomicAdd(&g_fill[d1.z], 1)] = s1.z;
        g_csrc[atomicAdd(&g_fill[d1.w], 1)] = s1.w;
    } else {
        for (int e = i8; e < E; e++)
            g_csrc[atomicAdd(&g_fill[dst[e]], 1)] = src[e];
    }
}

// ---------------------------------------------------------------------------
// Layer-1 GEMM: 4 nodes/warp, transposed padded weights in smem, FFMA2.
#define WT_PITCH (IN_DIM + 4)
__global__ void k_gemm1(const float* __restrict__ x, const float* __restrict__ W,
                        const float* __restrict__ al, const float* __restrict__ ar,
                        int N) {
    __shared__ float Wt[HID * WT_PITCH];
    for (int i = threadIdx.x; i < IN_DIM * HID; i += blockDim.x) {
        int k = i / HID, o = i % HID;
        Wt[o * WT_PITCH + k] = W[i];
    }
    __syncthreads();

    int warp = (blockIdx.x * blockDim.x + threadIdx.x) >> 5;
    int lane = threadIdx.x & 31;
    int n0 = warp * 4;
    if (n0 >= N) return;

    const float4* wv = (const float4*)(Wt + lane * WT_PITCH);
    const float4* x0 = (const float4*)(x + (size_t)n0 * IN_DIM);
    bool v1 = n0 + 1 < N, v2 = n0 + 2 < N, v3 = n0 + 3 < N;

    u64 a01[4] = {0, 0, 0, 0}, a23[4] = {0, 0, 0, 0};
#pragma unroll
    for (int k4 = 0; k4 < IN_DIM / 4; k4++) {
        float4 w = wv[k4];
        u64 w01 = pk2(w.x, w.y), w23 = pk2(w.z, w.w);
        float4 a = x0[k4];
        fma2(a01[0], pk2(a.x, a.y), w01);
        fma2(a23[0], pk2(a.z, a.w), w23);
        if (v1) {
            float4 b = x0[IN_DIM / 4 + k4];
            fma2(a01[1], pk2(b.x, b.y), w01);
            fma2(a23[1], pk2(b.z, b.w), w23);
        }
        if (v2) {
            float4 c = x0[2 * IN_DIM / 4 + k4];
            fma2(a01[2], pk2(c.x, c.y), w01);
            fma2(a23[2], pk2(c.z, c.w), w23);
        }
        if (v3) {
            float4 d = x0[3 * IN_DIM / 4 + k4];
            fma2(a01[3], pk2(d.x, d.y), w01);
            fma2(a23[3], pk2(d.z, d.w), w23);
        }
    }

    float alv = al[lane], arv = ar[lane];
#pragma unroll
    for (int i = 0; i < 4; i++) {
        if (n0 + i >= N) break;
        float2 p = upk2(a01[i]), q = upk2(a23[i]);
        float acc = (p.x + p.y) + (q.x + q.y);
        g_h[(size_t)(n0 + i) * HID + lane] = acc;
        float vl = acc * alv, vr = acc * arv;
#pragma unroll
        for (int o = 16; o; o >>= 1) {
            vl += __shfl_xor_sync(0xffffffffu, vl, o);
            vr += __shfl_xor_sync(0xffffffffu, vr, o);
        }
        if (lane == 0) { g_el[n0 + i] = vl; g_er[n0 + i] = vr; }
    }
}

// ---------------------------------------------------------------------------
// Fused layer-1 aggregation + ELU + layer-2 GEMM + layer-2 logits.
// One warp per dst node. Reads g_h/g_el/g_er, writes g_h2/g_el2/g_er2.
#define W2_PITCH 33   // (33*lane + k) % 32 == (lane + k) % 32 -> conflict-free
__global__ void k_agg1_gemm2(const float* __restrict__ b1,
                             const float* __restrict__ W2,
                             const float* __restrict__ al2,
                             const float* __restrict__ ar2, int N) {
    __shared__ float W2s[HID * W2_PITCH];
    for (int i = threadIdx.x; i < HID * HID; i += blockDim.x) {
        int k = i / HID, o = i % HID;
        W2s[o * W2_PITCH + k] = W2[i];
    }
    __syncthreads();

    int node = (blockIdx.x * blockDim.x + threadIdx.x) >> 5;
    int lane = threadIdx.x & 31;
    if (node >= N) return;

    int start = g_rowptr[node];
    int end   = g_rowptr[node + 1];
    int deg   = end - start;
    float erd = g_er[node];

    int eg = lane >> 3;   // 0..3
    int dl = lane & 7;    // 0..7

    u64 acc01 = 0, acc23 = 0;
    float denp = 0.f;

    for (int base = start; base < end; base += 32) {
        int idx = base + lane;
        bool valid = idx < end;
        int s_l = valid ? g_csrc[idx] : 0;
        float ex_l = 0.f;
        if (valid) {
            float t = g_el[s_l] + erd;
            t = (t > 0.f) ? t : NEG_SLOPE * t;
            ex_l = __expf(t);
        }
        denp += ex_l;

        int cnt = end - base; if (cnt > 32) cnt = 32;
        for (int j0 = 0; j0 < cnt; j0 += 8) {
            int jA = j0 + eg, jB = j0 + 4 + eg;
            int   sA = __shfl_sync(0xffffffffu, s_l, jA);
            float xA = __shfl_sync(0xffffffffu, ex_l, jA);
            int   sB = __shfl_sync(0xffffffffu, s_l, jB);
            float xB = __shfl_sync(0xffffffffu, ex_l, jB);
            float4 hA = *(const float4*)(g_h + (size_t)sA * HID + dl * 4);
            float4 hB = *(const float4*)(g_h + (size_t)sB * HID + dl * 4);
            u64 xA2 = pk2(xA, xA), xB2 = pk2(xB, xB);
            fma2(acc01, xA2, pk2(hA.x, hA.y));
            fma2(acc23, xA2, pk2(hA.z, hA.w));
            fma2(acc01, xB2, pk2(hB.x, hB.y));
            fma2(acc23, xB2, pk2(hB.z, hB.w));
        }
    }

    float2 p = upk2(acc01), q = upk2(acc23);
    float4 acc = {p.x, p.y, q.x, q.y};
#pragma unroll
    for (int off = 8; off <= 16; off <<= 1) {
        acc.x += __shfl_xor_sync(0xffffffffu, acc.x, off);
        acc.y += __shfl_xor_sync(0xffffffffu, acc.y, off);
        acc.z += __shfl_xor_sync(0xffffffffu, acc.z, off);
        acc.w += __shfl_xor_sync(0xffffffffu, acc.w, off);
    }
#pragma unroll
    for (int off = 16; off; off >>= 1)
        denp += __shfl_xor_sync(0xffffffffu, denp, off);

    // hmid row (ELU(acc/den + b1)) lives on lanes eg==0 as float4
    float4 r = {0.f, 0.f, 0.f, 0.f};
    if (eg == 0) {
        float inv = (deg > 0) ? 1.f / denp : 0.f;
        float4 b = *(const float4*)(b1 + dl * 4);
        r.x = acc.x * inv + b.x;
        r.y = acc.y * inv + b.y;
        r.z = acc.z * inv + b.z;
        r.w = acc.w * inv + b.w;
        r.x = (r.x > 0.f) ? r.x : expm1f(r.x);
        r.y = (r.y > 0.f) ? r.y : expm1f(r.y);
        r.z = (r.z > 0.f) ? r.z : expm1f(r.z);
        r.w = (r.w > 0.f) ? r.w : expm1f(r.w);
    }

    // in-register gemm2: h2[lane] = sum_k hmid[k] * W2t[lane][k]
    const float* wrow = W2s + lane * W2_PITCH;
    float acc2 = 0.f;
#pragma unroll
    for (int k4 = 0; k4 < 8; k4++) {
        float hx = __shfl_sync(0xffffffffu, r.x, k4);
        float hy = __shfl_sync(0xffffffffu, r.y, k4);
        float hz = __shfl_sync(0xffffffffu, r.z, k4);
        float hw = __shfl_sync(0xffffffffu, r.w, k4);
        acc2 += hx * wrow[4 * k4 + 0] + hy * wrow[4 * k4 + 1]
              + hz * wrow[4 * k4 + 2] + hw * wrow[4 * k4 + 3];
    }
    g_h2[(size_t)node * HID + lane] = acc2;

    float vl = acc2 * al2[lane], vr = acc2 * ar2[lane];
#pragma unroll
    for (int o = 16; o; o >>= 1) {
        vl += __shfl_xor_sync(0xffffffffu, vl, o);
        vr += __shfl_xor_sync(0xffffffffu, vr, o);
    }
    if (lane == 0) { g_el2[node] = vl; g_er2[node] = vr; }
}

// ---------------------------------------------------------------------------
// Layer-2 aggregation: reads g_h2/g_el2/g_er2, writes out (+b2).
__global__ void k_agg2(float* __restrict__ out, const float* __restrict__ b2, int N) {
    int node = (blockIdx.x * blockDim.x + threadIdx.x) >> 5;
    int lane = threadIdx.x & 31;
    if (node >= N) return;

    int start = g_rowptr[node];
    int end   = g_rowptr[node + 1];
    int deg   = end - start;
    float erd = g_er2[node];

    int eg = lane >> 3;
    int dl = lane & 7;

    u64 acc01 = 0, acc23 = 0;
    float denp = 0.f;

    for (int base = start; base < end; base += 32) {
        int idx = base + lane;
        bool valid = idx < end;
        int s_l = valid ? g_csrc[idx] : 0;
        float ex_l = 0.f;
        if (valid) {
            float t = g_el2[s_l] + erd;
            t = (t > 0.f) ? t : NEG_SLOPE * t;
            ex_l = __expf(t);
        }
        denp += ex_l;

        int cnt = end - base; if (cnt > 32) cnt = 32;
        for (int j0 = 0; j0 < cnt; j0 += 8) {
            int jA = j0 + eg, jB = j0 + 4 + eg;
            int   sA = __shfl_sync(0xffffffffu, s_l, jA);
            float xA = __shfl_sync(0xffffffffu, ex_l, jA);
            int   sB = __shfl_sync(0xffffffffu, s_l, jB);
            float xB = __shfl_sync(0xffffffffu, ex_l, jB);
            float4 hA = *(const float4*)(g_h2 + (size_t)sA * HID + dl * 4);
            float4 hB = *(const float4*)(g_h2 + (size_t)sB * HID + dl * 4);
            u64 xA2 = pk2(xA, xA), xB2 = pk2(xB, xB);
            fma2(acc01, xA2, pk2(hA.x, hA.y));
            fma2(acc23, xA2, pk2(hA.z, hA.w));
            fma2(acc01, xB2, pk2(hB.x, hB.y));
            fma2(acc23, xB2, pk2(hB.z, hB.w));
        }
    }

    float2 p = upk2(acc01), q = upk2(acc23);
    float4 acc = {p.x, p.y, q.x, q.y};
#pragma unroll
    for (int off = 8; off <= 16; off <<= 1) {
        acc.x += __shfl_xor_sync(0xffffffffu, acc.x, off);
        acc.y += __shfl_xor_sync(0xffffffffu, acc.y, off);
        acc.z += __shfl_xor_sync(0xffffffffu, acc.z, off);
        acc.w += __shfl_xor_sync(0xffffffffu, acc.w, off);
    }
#pragma unroll
    for (int off = 16; off; off >>= 1)
        denp += __shfl_xor_sync(0xffffffffu, denp, off);

    if (eg == 0) {
        float inv = (deg > 0) ? 1.f / denp : 0.f;
        float4 b = *(const float4*)(b2 + dl * 4);
        float4 r;
        r.x = acc.x * inv + b.x;
        r.y = acc.y * inv + b.y;
        r.z = acc.z * inv + b.z;
        r.w = acc.w * inv + b.w;
        *(float4*)(out + (size_t)node * HID + dl * 4) = r;
    }
}

// ---------------------------------------------------------------------------
extern "C" void kernel_launch(void* const* d_in, const int* in_sizes, int n_in,
                              void* d_out, int out_size) {
    const float* features = (const float*)d_in[0];
    const int*   src      = (const int*)d_in[1];
    const int*   dst      = (const int*)d_in[2];
    const float* W1  = (const float*)d_in[3];
    const float* al1 = (const float*)d_in[4];
    const float* ar1 = (const float*)d_in[5];
    const float* b1  = (const float*)d_in[6];
    const float* W2  = (const float*)d_in[7];
    const float* al2 = (const float*)d_in[8];
    const float* ar2 = (const float*)d_in[9];
    const float* b2  = (const float*)d_in[10];
    float* out = (float*)d_out;

    int N = in_sizes[0] / IN_DIM;
    int E = in_sizes[1];

    int gridNodeWarps = (N * 32 + TB - 1) / TB;
    int gridGemm      = (((N + 3) / 4) * 32 + TB - 1) / TB;
    int gridE4 = ((E + 3) / 4 + TB - 1) / TB;
    int gridE8 = ((E + 7) / 8 + TB - 1) / TB;
    int nb = (N + SB - 1) / SB;

    int* cntp = nullptr;
    cudaGetSymbolAddress((void**)&cntp, g_cnt);

    // fork: gemm1 runs concurrently with the CSR build chain
    cudaStream_t s1;
    cudaStreamCreateWithFlags(&s1, cudaStreamNonBlocking);
    cudaEvent_t e0, e1;
    cudaEventCreateWithFlags(&e0, cudaEventDisableTiming);
    cudaEventCreateWithFlags(&e1, cudaEventDisableTiming);

    cudaEventRecord(e0, 0);
    cudaStreamWaitEvent(s1, e0, 0);
    k_gemm1<<<gridGemm, TB, 0, s1>>>(features, W1, al1, ar1, N);
    cudaEventRecord(e1, s1);

    // main stream: CSR build
    cudaMemsetAsync(cntp, 0, (size_t)N * sizeof(int));
    k_hist<<<gridE4, TB>>>(dst, E);
    k_scan1<<<nb, SB>>>(N);
    k_scan3<<<nb, SB>>>(N, E);
    k_scatter<<<gridE8, TB>>>(src, dst, E);

    // join, then fused agg1+gemm2, then agg2
    cudaStreamWaitEvent(0, e1, 0);
    k_agg1_gemm2<<<gridNodeWarps, TB>>>(b1, W2, al2, ar2, N);
    k_agg2<<<gridNodeWarps, TB>>>(out, b2, N);

    cudaEventDestroy(e0);
    cudaEventDestroy(e1);
    cudaStreamDestroy(s1);
}